// round 16
// baseline (speedup 1.0000x reference)
#include <cuda_runtime.h>
#include <cuda_bf16.h>
#include <cstdint>

#define EPS_F      1e-8f
#define EPS4_F     4e-8f                 // 4*EPS  (clip on raw squares)
#define EPS16_F    1.6e-7f               // 16*EPS (clip on z product)
#define EPS64_F    6.4e-7f               // 64*EPS (clip on raw det)
#define TAU4_INV   13.333333333333334f   // 4/0.3 (cube-root 1/64 folded in)
#define LOG2E_F    1.4426950408889634f

static constexpr int NT     = 256;
static constexpr int WPB    = NT / 32;    // 8 warps per CTA
static constexpr int NB1    = 740;        // 148 SMs * 5 (smem: 43KB/CTA)
static constexpr int STAGES = 3;          // prefetch distance 2
static constexpr int WT_F4  = 56;         // float4 per tensor per 32-box warp-tile
static constexpr int CHUNK  = 4;          // finer steal granule: halves tail skew vs 8

__device__ float2       g_partials[NB1];
__device__ unsigned int g_done_count;
__device__ unsigned int g_next_tile;      // work-steal counter (reset each run)

__device__ __forceinline__ float warp_sum(float v) {
    #pragma unroll
    for (int off = 16; off > 0; off >>= 1)
        v += __shfl_xor_sync(0xFFFFFFFFu, v, off);
    return v;
}
__device__ __forceinline__ float fsqrt_ap(float x) {
    float r; asm("sqrt.approx.f32 %0, %1;" : "=f"(r) : "f"(x)); return r;
}
__device__ __forceinline__ float ex2_ap(float x) {
    float r; asm("ex2.approx.f32 %0, %1;" : "=f"(r) : "f"(x)); return r;
}
__device__ __forceinline__ float lg2_ap(float x) {
    float r; asm("lg2.approx.f32 %0, %1;" : "=f"(r) : "f"(x)); return r;
}
__device__ __forceinline__ uint32_t smem_u32(const void* p) {
    return (uint32_t)__cvta_generic_to_shared(p);
}
__device__ __forceinline__ void cp16(uint32_t dst, const void* src) {
    asm volatile("cp.async.cg.shared.global [%0], [%1], 16;" :: "r"(dst), "l"(src));
}

// per-box loss; covariance factor 0.25 folded out algebraically
__device__ __forceinline__ void box_loss(
    const float* __restrict__ p, const float* __restrict__ g,
    float& lsum, float& msum)
{
    float p0 = p[0], p1 = p[1], p2 = p[2], p3 = p[3], p4v = p[4], p5 = p[5], p6 = p[6];
    float g0 = g[0], g1 = g[1], g2 = g[2], g3 = g[3], g4v = g[4], g5 = g[5], g6 = g[6];

    float dx = p0 - g0, dy = p1 - g1, dz = p2 - g2;
    float mu = fmaf(dx, dx, fmaf(dy, dy, dz * dz));

    float tp = p3 * p3, up = p4v * p4v, vp = p5 * p5;
    float tt = g3 * g3, ut = g4v * g4v, vt = g5 * g5;

    float mtp = fmaxf(tp, EPS4_F);
    float mup = fmaxf(up, EPS4_F);
    float mvp = fmaxf(vp, EPS4_F);

    float cd = __cosf(p6 - g6);
    float cc = cd * cd;
    float ss = 1.0f - cc;
    float t1 = mtp * tt, t2 = mup * ut;
    float t3 = mtp * ut, t4 = mup * tt;
    float trM = fmaf(cc, t1 + t2, ss * (t3 + t4));
    float trS = fsqrt_ap(fmaf(2.0f, fsqrt_ap(t1 * t2), trM));   // sqrt(l1)+sqrt(l2)

    float sz = fsqrt_ap(fmaxf(mvp * vt, EPS16_F));

    float traces = (tp + up + vp) + (tt + ut + vt);
    float w2 = fmaf(0.25f, traces - 2.0f * (trS + sz), mu);

    float detr = fmaxf(tt * ut * vt, EPS64_F);
    float invd = ex2_ap(lg2_ap(detr) * (-1.0f / 3.0f)) * TAU4_INV;

    float loss = 1.0f - ex2_ap(-w2 * invd * LOG2E_F);
    if (g0 != 0.0f) { lsum += loss; msum += 1.0f; }
}

__global__ __launch_bounds__(NT) void gwd_fused(
    const float* __restrict__ pred,
    const float* __restrict__ gt,
    float* __restrict__ out,
    int total)
{
    // per-warp triple-buffered staging: [stage][warp][pred|gt][56 float4]
    __shared__ __align__(16) float4 sbuf[STAGES][WPB][2][WT_F4];

    const int lane = threadIdx.x & 31;
    const int wid  = threadIdx.x >> 5;

    const float4* __restrict__ p4 = (const float4*)pred;
    const float4* __restrict__ g4 = (const float4*)gt;

    const int  nwt  = total >> 5;                    // full 32-box warp-tiles
    const bool lo24 = (lane < WT_F4 - 32);           // lanes 0..23 carry a 2nd float4

    float lsum = 0.0f;
    float msum = 0.0f;

    // ---- warp-level work stealing: grab CHUNK contiguous tiles at a time ----
    int cur = 0, endt = 0;
    bool done = false;
    auto next_tile = [&]() -> int {
        if (cur >= endt) {
            if (done) return -1;
            int base;
            if (lane == 0) base = (int)atomicAdd(&g_next_tile, (unsigned)CHUNK);
            base = __shfl_sync(0xFFFFFFFFu, base, 0);
            if (base >= nwt) { done = true; return -1; }
            cur  = base;
            endt = min(base + CHUNK, nwt);
        }
        return cur++;
    };

    auto stage = [&](int buf, int wt) {
        const float4* ps = p4 + 56ll * wt;
        const float4* gs = g4 + 56ll * wt;
        const uint32_t dp = smem_u32(&sbuf[buf][wid][0][0]);
        const uint32_t dg = smem_u32(&sbuf[buf][wid][1][0]);
        cp16(dp + lane * 16u, ps + lane);
        cp16(dg + lane * 16u, gs + lane);
        if (lo24) {
            cp16(dp + (32u + lane) * 16u, ps + 32 + lane);
            cp16(dg + (32u + lane) * 16u, gs + 32 + lane);
        }
    };

    // tile-index ring: which tile lives in which buffer
    int tiles[STAGES];
    tiles[0] = next_tile();
    if (tiles[0] >= 0) stage(0, tiles[0]);
    asm volatile("cp.async.commit_group;");
    tiles[1] = next_tile();
    if (tiles[1] >= 0) stage(1, tiles[1]);
    asm volatile("cp.async.commit_group;");
    tiles[2] = -2;   // sentinel: not yet staged

    int buf = 0;
    while (tiles[buf] >= 0) {
        // wait for the oldest in-flight group (this buffer's); 2 newer stay in flight
        asm volatile("cp.async.wait_group 2;");
        __syncwarp();

        const float* pl = (const float*)&sbuf[buf][wid][0][0] + 7 * lane;
        const float* gl = (const float*)&sbuf[buf][wid][1][0] + 7 * lane;
        box_loss(pl, gl, lsum, msum);   // stride-7 LDS: gcd(7,32)=1, conflict-free

        __syncwarp();                   // all lanes done reading this buffer

        // refill this buffer with the next stolen tile
        const int tn = next_tile();
        if (tn >= 0) stage(buf, tn);
        asm volatile("cp.async.commit_group;");
        tiles[buf] = tn;

        buf = (buf == STAGES - 1) ? 0 : buf + 1;
    }
    asm volatile("cp.async.wait_group 0;");   // drain any stragglers

    // ragged tail boxes (0 for this shape; kept for generality)
    if ((nwt << 5) != total && blockIdx.x == 0 && wid == 0) {
        for (int b = (nwt << 5) + lane; b < total; b += 32) {
            const float* p = pred + 7ll * b;
            const float* g = gt   + 7ll * b;
            float pr[7], gr[7];
            #pragma unroll
            for (int k = 0; k < 7; k++) { pr[k] = __ldg(p + k); gr[k] = __ldg(g + k); }
            box_loss(pr, gr, lsum, msum);
        }
    }

    // block reduction
    lsum = warp_sum(lsum);
    msum = warp_sum(msum);

    __shared__ float sl[WPB];
    __shared__ float sm[WPB];
    if (lane == 0) { sl[wid] = lsum; sm[wid] = msum; }
    __syncthreads();

    __shared__ bool is_last;
    if (threadIdx.x == 0) {
        float vl = 0.0f, vm = 0.0f;
        #pragma unroll
        for (int w = 0; w < WPB; w++) { vl += sl[w]; vm += sm[w]; }
        g_partials[blockIdx.x] = make_float2(vl, vm);
        __threadfence();
        unsigned int ticket = atomicAdd(&g_done_count, 1u);
        is_last = (ticket == (unsigned)(gridDim.x - 1));
    }
    __syncthreads();

    // last block finalizes (deterministic order over blocks)
    if (is_last) {
        double l = 0.0, m = 0.0;
        for (int i = threadIdx.x; i < (int)gridDim.x; i += NT) {
            float2 v = g_partials[i];
            l += (double)v.x;
            m += (double)v.y;
        }
        #pragma unroll
        for (int off = 16; off > 0; off >>= 1) {
            l += __shfl_xor_sync(0xFFFFFFFFu, l, off);
            m += __shfl_xor_sync(0xFFFFFFFFu, m, off);
        }
        __shared__ double dl[WPB];
        __shared__ double dm[WPB];
        if (lane == 0) { dl[wid] = l; dm[wid] = m; }
        __syncthreads();
        if (threadIdx.x == 0) {
            double vl = 0.0, vm = 0.0;
            #pragma unroll
            for (int w = 0; w < WPB; w++) { vl += dl[w]; vm += dm[w]; }
            out[0] = (float)(vl / (vm + (double)EPS_F));
            g_done_count = 0;   // reset for next graph replay
            g_next_tile  = 0;   // reset work-steal counter
        }
    }
}

extern "C" void kernel_launch(void* const* d_in, const int* in_sizes, int n_in,
                              void* d_out, int out_size)
{
    const float* pred = (const float*)d_in[0];
    const float* gt   = (const float*)d_in[1];
    float* out = (float*)d_out;

    int total = in_sizes[0] / 7;

    gwd_fused<<<NB1, NT>>>(pred, gt, out, total);
}

// round 17
// speedup vs baseline: 1.1555x; 1.1555x over previous
#include <cuda_runtime.h>
#include <cuda_bf16.h>
#include <cstdint>

#define EPS_F      1e-8f
#define EPS4_F     4e-8f                 // 4*EPS  (clip on raw squares)
#define EPS16_F    1.6e-7f               // 16*EPS (clip on z product)
#define EPS64_F    6.4e-7f               // 64*EPS (clip on raw det)
#define TAU4_INV   13.333333333333334f   // 4/0.3 (cube-root 1/64 folded in)
#define LOG2E_F    1.4426950408889634f

static constexpr int NT     = 256;
static constexpr int WPB    = NT / 32;    // 8 warps per CTA
static constexpr int NB1    = 740;        // 148 SMs * 5 (smem: 43KB/CTA)
static constexpr int STAGES = 3;          // prefetch distance 2
static constexpr int WT_F4  = 56;         // float4 per tensor per 32-box warp-tile
static constexpr int CHUNK  = 8;          // measured optimum (4 -> 17.1, 8 -> 14.8, 16 -> 15.1)

__device__ float2       g_partials[NB1];
__device__ unsigned int g_done_count;
__device__ unsigned int g_next_tile;      // work-steal counter (reset each run)

__device__ __forceinline__ float warp_sum(float v) {
    #pragma unroll
    for (int off = 16; off > 0; off >>= 1)
        v += __shfl_xor_sync(0xFFFFFFFFu, v, off);
    return v;
}
__device__ __forceinline__ float fsqrt_ap(float x) {
    float r; asm("sqrt.approx.f32 %0, %1;" : "=f"(r) : "f"(x)); return r;
}
__device__ __forceinline__ float ex2_ap(float x) {
    float r; asm("ex2.approx.f32 %0, %1;" : "=f"(r) : "f"(x)); return r;
}
__device__ __forceinline__ float lg2_ap(float x) {
    float r; asm("lg2.approx.f32 %0, %1;" : "=f"(r) : "f"(x)); return r;
}
__device__ __forceinline__ uint32_t smem_u32(const void* p) {
    return (uint32_t)__cvta_generic_to_shared(p);
}
__device__ __forceinline__ void cp16(uint32_t dst, const void* src) {
    asm volatile("cp.async.cg.shared.global [%0], [%1], 16;" :: "r"(dst), "l"(src));
}

// per-box loss; covariance factor 0.25 folded out algebraically
__device__ __forceinline__ void box_loss(
    const float* __restrict__ p, const float* __restrict__ g,
    float& lsum, float& msum)
{
    float p0 = p[0], p1 = p[1], p2 = p[2], p3 = p[3], p4v = p[4], p5 = p[5], p6 = p[6];
    float g0 = g[0], g1 = g[1], g2 = g[2], g3 = g[3], g4v = g[4], g5 = g[5], g6 = g[6];

    float dx = p0 - g0, dy = p1 - g1, dz = p2 - g2;
    float mu = fmaf(dx, dx, fmaf(dy, dy, dz * dz));

    float tp = p3 * p3, up = p4v * p4v, vp = p5 * p5;
    float tt = g3 * g3, ut = g4v * g4v, vt = g5 * g5;

    float mtp = fmaxf(tp, EPS4_F);
    float mup = fmaxf(up, EPS4_F);
    float mvp = fmaxf(vp, EPS4_F);

    float cd = __cosf(p6 - g6);
    float cc = cd * cd;
    float ss = 1.0f - cc;
    float t1 = mtp * tt, t2 = mup * ut;
    float t3 = mtp * ut, t4 = mup * tt;
    float trM = fmaf(cc, t1 + t2, ss * (t3 + t4));
    float trS = fsqrt_ap(fmaf(2.0f, fsqrt_ap(t1 * t2), trM));   // sqrt(l1)+sqrt(l2)

    float sz = fsqrt_ap(fmaxf(mvp * vt, EPS16_F));

    float traces = (tp + up + vp) + (tt + ut + vt);
    float w2 = fmaf(0.25f, traces - 2.0f * (trS + sz), mu);

    float detr = fmaxf(tt * ut * vt, EPS64_F);
    float invd = ex2_ap(lg2_ap(detr) * (-1.0f / 3.0f)) * TAU4_INV;

    float loss = 1.0f - ex2_ap(-w2 * invd * LOG2E_F);
    if (g0 != 0.0f) { lsum += loss; msum += 1.0f; }
}

__global__ __launch_bounds__(NT) void gwd_fused(
    const float* __restrict__ pred,
    const float* __restrict__ gt,
    float* __restrict__ out,
    int total)
{
    // per-warp triple-buffered staging: [stage][warp][pred|gt][56 float4]
    __shared__ __align__(16) float4 sbuf[STAGES][WPB][2][WT_F4];

    const int lane = threadIdx.x & 31;
    const int wid  = threadIdx.x >> 5;

    const float4* __restrict__ p4 = (const float4*)pred;
    const float4* __restrict__ g4 = (const float4*)gt;

    const int  nwt  = total >> 5;                    // full 32-box warp-tiles
    const bool lo24 = (lane < WT_F4 - 32);           // lanes 0..23 carry a 2nd float4

    float lsum = 0.0f;
    float msum = 0.0f;

    // ---- warp-level work stealing: grab CHUNK contiguous tiles at a time ----
    int cur = 0, endt = 0;
    bool done = false;
    auto next_tile = [&]() -> int {
        if (cur >= endt) {
            if (done) return -1;
            int base;
            if (lane == 0) base = (int)atomicAdd(&g_next_tile, (unsigned)CHUNK);
            base = __shfl_sync(0xFFFFFFFFu, base, 0);
            if (base >= nwt) { done = true; return -1; }
            cur  = base;
            endt = min(base + CHUNK, nwt);
        }
        return cur++;
    };

    auto stage = [&](int buf, int wt) {
        const float4* ps = p4 + 56ll * wt;
        const float4* gs = g4 + 56ll * wt;
        const uint32_t dp = smem_u32(&sbuf[buf][wid][0][0]);
        const uint32_t dg = smem_u32(&sbuf[buf][wid][1][0]);
        cp16(dp + lane * 16u, ps + lane);
        cp16(dg + lane * 16u, gs + lane);
        if (lo24) {
            cp16(dp + (32u + lane) * 16u, ps + 32 + lane);
            cp16(dg + (32u + lane) * 16u, gs + 32 + lane);
        }
    };

    // tile-index ring: which tile lives in which buffer
    int tiles[STAGES];
    tiles[0] = next_tile();
    if (tiles[0] >= 0) stage(0, tiles[0]);
    asm volatile("cp.async.commit_group;");
    tiles[1] = next_tile();
    if (tiles[1] >= 0) stage(1, tiles[1]);
    asm volatile("cp.async.commit_group;");
    tiles[2] = -2;   // sentinel: not yet staged

    int buf = 0;
    while (tiles[buf] >= 0) {
        // wait for the oldest in-flight group (this buffer's); 2 newer stay in flight
        asm volatile("cp.async.wait_group 2;");
        __syncwarp();

        const float* pl = (const float*)&sbuf[buf][wid][0][0] + 7 * lane;
        const float* gl = (const float*)&sbuf[buf][wid][1][0] + 7 * lane;
        box_loss(pl, gl, lsum, msum);   // stride-7 LDS: gcd(7,32)=1, conflict-free

        __syncwarp();                   // all lanes done reading this buffer

        // refill this buffer with the next stolen tile
        const int tn = next_tile();
        if (tn >= 0) stage(buf, tn);
        asm volatile("cp.async.commit_group;");
        tiles[buf] = tn;

        buf = (buf == STAGES - 1) ? 0 : buf + 1;
    }
    asm volatile("cp.async.wait_group 0;");   // drain any stragglers

    // ragged tail boxes (0 for this shape; kept for generality)
    if ((nwt << 5) != total && blockIdx.x == 0 && wid == 0) {
        for (int b = (nwt << 5) + lane; b < total; b += 32) {
            const float* p = pred + 7ll * b;
            const float* g = gt   + 7ll * b;
            float pr[7], gr[7];
            #pragma unroll
            for (int k = 0; k < 7; k++) { pr[k] = __ldg(p + k); gr[k] = __ldg(g + k); }
            box_loss(pr, gr, lsum, msum);
        }
    }

    // block reduction
    lsum = warp_sum(lsum);
    msum = warp_sum(msum);

    __shared__ float sl[WPB];
    __shared__ float sm[WPB];
    if (lane == 0) { sl[wid] = lsum; sm[wid] = msum; }
    __syncthreads();

    __shared__ bool is_last;
    if (threadIdx.x == 0) {
        float vl = 0.0f, vm = 0.0f;
        #pragma unroll
        for (int w = 0; w < WPB; w++) { vl += sl[w]; vm += sm[w]; }
        g_partials[blockIdx.x] = make_float2(vl, vm);
        __threadfence();
        unsigned int ticket = atomicAdd(&g_done_count, 1u);
        is_last = (ticket == (unsigned)(gridDim.x - 1));
    }
    __syncthreads();

    // last block finalizes (deterministic order over blocks)
    if (is_last) {
        double l = 0.0, m = 0.0;
        for (int i = threadIdx.x; i < (int)gridDim.x; i += NT) {
            float2 v = g_partials[i];
            l += (double)v.x;
            m += (double)v.y;
        }
        #pragma unroll
        for (int off = 16; off > 0; off >>= 1) {
            l += __shfl_xor_sync(0xFFFFFFFFu, l, off);
            m += __shfl_xor_sync(0xFFFFFFFFu, m, off);
        }
        __shared__ double dl[WPB];
        __shared__ double dm[WPB];
        if (lane == 0) { dl[wid] = l; dm[wid] = m; }
        __syncthreads();
        if (threadIdx.x == 0) {
            double vl = 0.0, vm = 0.0;
            #pragma unroll
            for (int w = 0; w < WPB; w++) { vl += dl[w]; vm += dm[w]; }
            out[0] = (float)(vl / (vm + (double)EPS_F));
            g_done_count = 0;   // reset for next graph replay
            g_next_tile  = 0;   // reset work-steal counter
        }
    }
}

extern "C" void kernel_launch(void* const* d_in, const int* in_sizes, int n_in,
                              void* d_out, int out_size)
{
    const float* pred = (const float*)d_in[0];
    const float* gt   = (const float*)d_in[1];
    float* out = (float*)d_out;

    int total = in_sizes[0] / 7;

    gwd_fused<<<NB1, NT>>>(pred, gt, out, total);
}